// round 16
// baseline (speedup 1.0000x reference)
#include <cuda_runtime.h>
#include <cuda_fp16.h>
#include <math.h>
#include <stdint.h>

// ---------------- problem constants ----------------
#define B_      8
#define H_      128
#define W_      128
#define DIM_    256
#define HEADS_  16
#define DH_     16
#define HW_     (H_*W_)            // 16384
#define M_TOTAL (B_*HW_)           // 131072
#define N_QKV   (3*DIM_)           // 768
#define SLICES  8

// ---------------- scratch (no allocs -> __device__ globals) ----------------
__device__ __half g_xh   [(size_t)M_TOTAL * DIM_];    // fp16 x
__device__ __half g_qkvh [(size_t)M_TOTAL * N_QKV];   // pre-conv qkv (fp16)
__device__ __half g_qkh  [(size_t)M_TOTAL * 2 * DIM_];// post-conv NORMALIZED q,k (fp16)
__device__ __half g_vh   [(size_t)M_TOTAL * DIM_];    // post-conv v (fp16)
__device__ float  g_part [SLICES * B_ * HEADS_ * DH_ * DH_];
__device__ float  g_attn [B_ * HEADS_ * DH_ * DH_];
__device__ __half g_wfTh [B_ * DIM_ * DIM_];          // fused W^T per batch (fp16)
__device__ __half g_wqkvTh[N_QKV * DIM_];             // w_qkv^T (fp16)
__device__ float2 g_statq[HW_];                        // {mean_q, rsqrt(var_q)}
__device__ float2 g_statk[HW_];                        // {mean_k, rsqrt(var_k)}

// ---------------- helpers ----------------
__device__ __forceinline__ uint32_t smem_u32(const void* p) {
    uint32_t a;
    asm("{ .reg .u64 t; cvta.to.shared.u64 t, %1; cvt.u32.u64 %0, t; }" : "=r"(a) : "l"(p));
    return a;
}
__device__ __forceinline__ void cp16(uint32_t daddr, const void* g) {
    asm volatile("cp.async.ca.shared.global [%0], [%1], 16;" :: "r"(daddr), "l"(g));
}
#define CP_COMMIT() asm volatile("cp.async.commit_group;" ::: "memory")
#define CP_WAIT(n)  asm volatile("cp.async.wait_group %0;" :: "n"(n) : "memory")

__device__ __forceinline__ void mma_f16(float* c, const uint32_t* a, const uint32_t* b) {
    asm volatile(
        "mma.sync.aligned.m16n8k16.row.col.f32.f16.f16.f32 "
        "{%0,%1,%2,%3}, {%4,%5,%6,%7}, {%8,%9}, {%0,%1,%2,%3};"
        : "+f"(c[0]), "+f"(c[1]), "+f"(c[2]), "+f"(c[3])
        : "r"(a[0]), "r"(a[1]), "r"(a[2]), "r"(a[3]), "r"(b[0]), "r"(b[1]));
}
__device__ __forceinline__ void ldsm_x4(uint32_t& r0, uint32_t& r1, uint32_t& r2, uint32_t& r3,
                                        uint32_t addr) {
    asm volatile("ldmatrix.sync.aligned.m8n8.x4.shared.b16 {%0,%1,%2,%3}, [%4];"
        : "=r"(r0), "=r"(r1), "=r"(r2), "=r"(r3) : "r"(addr));
}

// ---------------- fp16 mma.sync GEMM: SW64-swizzled staging, 3-stage cp.async ------
// CTA 128x128, 128 threads, 4 warps of 64x64. Rows are 64B (BK=32 fp16);
// smem offset = row*64 + ((chunk*16) ^ ((row&6)<<3))  [SW64 swizzle]
// -> conflict-free for BOTH cp.async 16B stores and LDSM reads.
#define TM_BM 128
#define TM_BN 128
#define TM_BK 32
#define TM_AREG  8192                          // A region bytes (128 rows * 64B)
#define TM_STAGE_B 16384                       // A + B per stage
#define TM_NSTAGE 3
#define TM_SMEM  (TM_NSTAGE * TM_STAGE_B)      // 49152 B (dynamic)

template <bool HALF_OUT>
__global__ __launch_bounds__(128, 2) void mgemm_k(
    const __half* __restrict__ A, int lda,
    const __half* __restrict__ Bt, int ldb, long long b_stride,
    void* __restrict__ Cv, int ldc,
    int rows_per_batch, int K)
{
    extern __shared__ __half smh[];

    const int tid  = threadIdx.x;
    const int lane = tid & 31;
    const int wid  = tid >> 5;                // 0..3
    const int wm   = wid & 1;                 // 2 m-slices of 64
    const int wn   = wid >> 1;                // 2 n-slices of 64
    const int gid  = lane >> 2;
    const int tig  = lane & 3;

    const int m0 = blockIdx.y * TM_BM;
    const int n0 = blockIdx.x * TM_BN;
    const int batch = m0 / rows_per_batch;
    const __half* Ap = A  + (size_t)m0 * lda;
    const __half* Bp = Bt + (size_t)batch * b_stride + (size_t)n0 * ldb;

    const uint32_t sbase = smem_u32(smh);

    // LDSM lane geometry (rows constant per lane; swizzle XOR constant per lane)
    const int arow  = (lane & 7) + ((lane >> 3) & 1) * 8;     // row within 16-tile
    const int asel  = ((lane >> 4) & 1) * 16;                 // 16B chunk select (k half)
    const int arowg = wm * 64 + arow;
    const uint32_t a_base = (uint32_t)(arowg * 64);
    const uint32_t a_xor  = (uint32_t)((arowg & 6) << 3);

    const int brow  = (lane & 7) + ((lane >> 4) & 1) * 8;
    const int bsel  = ((lane >> 3) & 1) * 16;
    const int browg = wn * 64 + brow;
    const uint32_t b_base = (uint32_t)(TM_AREG + browg * 64);
    const uint32_t b_xor  = (uint32_t)((browg & 6) << 3);

    float acc[4][8][4];
    #pragma unroll
    for (int mt = 0; mt < 4; mt++)
        #pragma unroll
        for (int nt = 0; nt < 8; nt++)
            #pragma unroll
            for (int r = 0; r < 4; r++) acc[mt][nt][r] = 0.f;

    const int nk = K / TM_BK;

    // per stage (128 threads): A 4 cp16/thread, B 4 cp16/thread; swizzled dst
    #define STAGE_LOAD(S, BUF) do {                                               \
        const __half* gA = Ap + (S) * TM_BK;                                       \
        const __half* gB = Bp + (S) * TM_BK;                                       \
        const uint32_t sb_ = sbase + (uint32_t)((BUF) * TM_STAGE_B);               \
        _Pragma("unroll")                                                          \
        for (int i = 0; i < 4; i++) {                                              \
            int idx = i * 128 + tid;                                               \
            int r = idx >> 2, c = idx & 3;                                         \
            uint32_t dst = sb_ + (uint32_t)(r * 64) +                              \
                           (uint32_t)(((c * 16) ^ ((r & 6) << 3)));                \
            cp16(dst, gA + (size_t)r * lda + c * 8);                               \
        }                                                                          \
        _Pragma("unroll")                                                          \
        for (int i = 0; i < 4; i++) {                                              \
            int idx = i * 128 + tid;                                               \
            int r = idx >> 2, c = idx & 3;                                         \
            uint32_t dst = sb_ + (uint32_t)(TM_AREG + r * 64) +                    \
                           (uint32_t)(((c * 16) ^ ((r & 6) << 3)));                \
            cp16(dst, gB + (size_t)r * ldb + c * 8);                               \
        }                                                                          \
        CP_COMMIT();                                                               \
    } while (0)

    STAGE_LOAD(0, 0);
    if (nk > 1) STAGE_LOAD(1, 1);

    for (int s = 0; s < nk; s++) {
        const int buf = s % TM_NSTAGE;
        if (s + 2 < nk) { STAGE_LOAD(s + 2, (s + 2) % TM_NSTAGE); CP_WAIT(2); }
        else            { CP_WAIT(0); }
        __syncthreads();

        const uint32_t stg = sbase + (uint32_t)(buf * TM_STAGE_B);

        #pragma unroll
        for (int ks = 0; ks < 2; ks++) {
            const uint32_t ka = (uint32_t)((ks * 32 + asel)) ^ a_xor;   // swizzled chunk
            const uint32_t kb = (uint32_t)((ks * 32 + bsel)) ^ b_xor;
            uint32_t bf[8][2];
            #pragma unroll
            for (int nt2 = 0; nt2 < 4; nt2++)
                ldsm_x4(bf[nt2*2][0], bf[nt2*2][1], bf[nt2*2+1][0], bf[nt2*2+1][1],
                        stg + b_base + (uint32_t)(nt2 * 16 * 64) + kb);
            #pragma unroll
            for (int mt = 0; mt < 4; mt++) {
                uint32_t af[4];
                ldsm_x4(af[0], af[1], af[2], af[3],
                        stg + a_base + (uint32_t)(mt * 16 * 64) + ka);
                #pragma unroll
                for (int nt = 0; nt < 8; nt++)
                    mma_f16(acc[mt][nt], af, bf[nt]);
            }
        }
        __syncthreads();
    }

    #pragma unroll
    for (int mt = 0; mt < 4; mt++) {
        #pragma unroll
        for (int nt = 0; nt < 8; nt++) {
            int row = m0 + wm * 64 + mt * 16 + gid;
            int col = n0 + wn * 64 + nt * 8 + tig * 2;
            if (HALF_OUT) {
                __half* C = (__half*)Cv;
                *(__half2*)(C + (size_t)row * ldc + col) =
                    __floats2half2_rn(acc[mt][nt][0], acc[mt][nt][1]);
                *(__half2*)(C + (size_t)(row + 8) * ldc + col) =
                    __floats2half2_rn(acc[mt][nt][2], acc[mt][nt][3]);
            } else {
                float* C = (float*)Cv;
                *(float2*)(C + (size_t)row * ldc + col) =
                    make_float2(acc[mt][nt][0], acc[mt][nt][1]);
                *(float2*)(C + (size_t)(row + 8) * ldc + col) =
                    make_float2(acc[mt][nt][2], acc[mt][nt][3]);
            }
        }
    }
}

// ---------------- cvt x -> fp16 copy ----------------
__global__ void cvt_x_k(const float* __restrict__ x, __half* __restrict__ xh) {
    size_t idx = (size_t)blockIdx.x * blockDim.x + threadIdx.x;
    if (idx >= ((size_t)M_TOTAL * DIM_) / 4) return;
    float4 v = ((const float4*)x)[idx];
    __half2 h0 = __floats2half2_rn(v.x, v.y);
    __half2 h1 = __floats2half2_rn(v.z, v.w);
    ((uint2*)xh)[idx] = make_uint2(*(uint32_t*)&h0, *(uint32_t*)&h1);
}

// ---------------- transpose + cvt + stat tables ----------------
__global__ void transp_k(const float* __restrict__ w, __half* __restrict__ wT) {
    int idx = blockIdx.x * blockDim.x + threadIdx.x;
    if (idx >= N_QKV * DIM_) return;
    int n = idx / DIM_, k = idx % DIM_;
    wT[idx] = __float2half_rn(w[(size_t)k * N_QKV + n]);
}

__global__ void stats_k(const float* __restrict__ mq, const float* __restrict__ vq,
                        const float* __restrict__ mk, const float* __restrict__ vk,
                        float2* __restrict__ sq, float2* __restrict__ sk) {
    int s = blockIdx.x * blockDim.x + threadIdx.x;
    if (s >= HW_) return;
    sq[s] = make_float2(mq[s], rsqrtf(vq[s]));
    sk[s] = make_float2(mk[s], rsqrtf(vk[s]));
}

// ---------------- depthwise 3x3 conv (fp16 in) + q,k normalize, fp16 outputs -------
__global__ __launch_bounds__(256) void dwconv_k(
    const __half* __restrict__ in, const float* __restrict__ w,
    __half* __restrict__ qkh, __half* __restrict__ vh,
    const float2* __restrict__ statq, const float2* __restrict__ statk)
{
    __shared__ float sm[10][34][16];

    const int bx = blockIdx.x;
    const int by = blockIdx.y;
    const int bz = blockIdx.z;
    const int b  = bz / 48, g48 = bz % 48;
    const int cbase = g48 * 16;
    const bool is_v = (cbase >= 2 * DIM_);
    const float2* stats = (cbase >= DIM_) ? statk : statq;

    const int tid = threadIdx.x;

    for (int i = tid; i < 10 * 34 * 2; i += 256) {
        int c8 = i & 1;
        int x  = (i >> 1) % 34;
        int y  = (i >> 1) / 34;
        int gy = by * 8 - 1 + y, gx = bx * 32 - 1 + x;
        float f[8] = {0.f, 0.f, 0.f, 0.f, 0.f, 0.f, 0.f, 0.f};
        if ((unsigned)gy < (unsigned)H_ && (unsigned)gx < (unsigned)W_) {
            uint4 u = *(const uint4*)(in + ((size_t)(b * H_ + gy) * W_ + gx) * N_QKV + cbase + c8 * 8);
            float2 f0 = __half22float2(*(__half2*)&u.x);
            float2 f1 = __half22float2(*(__half2*)&u.y);
            float2 f2 = __half22float2(*(__half2*)&u.z);
            float2 f3 = __half22float2(*(__half2*)&u.w);
            f[0] = f0.x; f[1] = f0.y; f[2] = f1.x; f[3] = f1.y;
            f[4] = f2.x; f[5] = f2.y; f[6] = f3.x; f[7] = f3.y;
        }
        float* d = &sm[y][x][c8 * 8];
        *(float4*)d       = make_float4(f[0], f[1], f[2], f[3]);
        *(float4*)(d + 4) = make_float4(f[4], f[5], f[6], f[7]);
    }

    const int c2s = tid & 7;
    const int xo  = tid >> 3;

    float2 wv[9];
    #pragma unroll
    for (int t = 0; t < 9; t++)
        wv[t] = *(const float2*)(w + (size_t)t * N_QKV + cbase + c2s * 2);
    __syncthreads();

    float2 rA[3], rB[3], rC[3];
    #pragma unroll
    for (int dx = 0; dx < 3; dx++) {
        rA[dx] = *(const float2*)&sm[0][xo + dx][c2s * 2];
        rB[dx] = *(const float2*)&sm[1][xo + dx][c2s * 2];
    }

    #pragma unroll
    for (int yo = 0; yo < 8; yo++) {
        #pragma unroll
        for (int dx = 0; dx < 3; dx++)
            rC[dx] = *(const float2*)&sm[yo + 2][xo + dx][c2s * 2];

        float2 acc = make_float2(0.f, 0.f);
        #pragma unroll
        for (int dx = 0; dx < 3; dx++) {
            acc.x += rA[dx].x * wv[dx].x;     acc.y += rA[dx].y * wv[dx].y;
        }
        #pragma unroll
        for (int dx = 0; dx < 3; dx++) {
            acc.x += rB[dx].x * wv[3 + dx].x; acc.y += rB[dx].y * wv[3 + dx].y;
        }
        #pragma unroll
        for (int dx = 0; dx < 3; dx++) {
            acc.x += rC[dx].x * wv[6 + dx].x; acc.y += rC[dx].y * wv[6 + dx].y;
        }

        int gy = by * 8 + yo, gx = bx * 32 + xo;
        size_t pix = (size_t)(b * H_ + gy) * W_ + gx;

        if (is_v) {
            *(__half2*)(vh + pix * DIM_ + (cbase - 2 * DIM_) + c2s * 2) =
                __floats2half2_rn(acc.x, acc.y);
        } else {
            float2 mv = stats[gy * W_ + gx];
            acc.x = (acc.x - mv.x) * mv.y;
            acc.y = (acc.y - mv.x) * mv.y;
            *(__half2*)(qkh + pix * (2 * DIM_) + cbase + c2s * 2) =
                __floats2half2_rn(acc.x, acc.y);
        }

        #pragma unroll
        for (int dx = 0; dx < 3; dx++) { rA[dx] = rB[dx]; rB[dx] = rC[dx]; }
    }
}

// ---------------- attention partials from fp16 normalized q,k ----------------
__global__ __launch_bounds__(256) void attn_part_k(
    const __half* __restrict__ qkh, float* __restrict__ part)
{
    const int bh = blockIdx.x;
    const int sl = blockIdx.y;
    const int b = bh >> 4, h = bh & 15;
    __shared__ float qs[64][16];
    __shared__ float ks[64][16];
    __shared__ float red[16][16][16];

    const int tid  = threadIdx.x;
    const int tile = tid & 15;
    const int g    = tid >> 4;
    const int it   = tile >> 2, jt = tile & 3;
    const int lrow = tid >> 2;
    const int lseg = tid & 3;
    const __half* base = qkh + (size_t)b * HW_ * (2 * DIM_) + h * DH_;

    float acc[4][4];
    #pragma unroll
    for (int a = 0; a < 4; a++)
        #pragma unroll
        for (int c = 0; c < 4; c++) acc[a][c] = 0.f;

    const int s_beg = sl * (HW_ / SLICES), s_end = s_beg + HW_ / SLICES;

    for (int s0 = s_beg; s0 < s_end; s0 += 64) {
        int s = s0 + lrow;
        const __half* pr = base + (size_t)s * (2 * DIM_);
        uint4 u;
        if (lseg < 2) u = *(const uint4*)(pr + lseg * 8);
        else          u = *(const uint4*)(pr + DIM_ + (lseg - 2) * 8);
        float* dst = (lseg < 2) ? &qs[lrow][(lseg & 1) * 8] : &ks[lrow][(lseg & 1) * 8];
        float2 f0 = __half22float2(*(__half2*)&u.x);
        float2 f1 = __half22float2(*(__half2*)&u.y);
        float2 f2 = __half22float2(*(__half2*)&u.z);
        float2 f3 = __half22float2(*(__half2*)&u.w);
        dst[0] = f0.x; dst[1] = f0.y; dst[2] = f1.x; dst[3] = f1.y;
        dst[4] = f2.x; dst[5] = f2.y; dst[6] = f3.x; dst[7] = f3.y;
        __syncthreads();

        #pragma unroll
        for (int t = 0; t < 4; t++) {
            int ss = g + t * 16;
            float4 kf = *(const float4*)&ks[ss][it * 4];
            float4 qf = *(const float4*)&qs[ss][jt * 4];
            acc[0][0] += kf.x * qf.x; acc[0][1] += kf.x * qf.y;
            acc[0][2] += kf.x * qf.z; acc[0][3] += kf.x * qf.w;
            acc[1][0] += kf.y * qf.x; acc[1][1] += kf.y * qf.y;
            acc[1][2] += kf.y * qf.z; acc[1][3] += kf.y * qf.w;
            acc[2][0] += kf.z * qf.x; acc[2][1] += kf.z * qf.y;
            acc[2][2] += kf.z * qf.z; acc[2][3] += kf.z * qf.w;
            acc[3][0] += kf.w * qf.x; acc[3][1] += kf.w * qf.y;
            acc[3][2] += kf.w * qf.z; acc[3][3] += kf.w * qf.w;
        }
        __syncthreads();
    }

    #pragma unroll
    for (int a = 0; a < 4; a++)
        #pragma unroll
        for (int c = 0; c < 4; c++)
            red[g][it * 4 + a][jt * 4 + c] = acc[a][c];
    __syncthreads();

    const int i2 = tid >> 4, j2 = tid & 15;
    float r = 0.f;
    #pragma unroll
    for (int gg = 0; gg < 16; gg++) r += red[gg][i2][j2];
    part[((size_t)(sl * (B_*HEADS_) + bh)) * 256 + i2 * 16 + j2] = r;
}

// ---------------- reduce slices + temperature + softmax(axis=-2) ----------------
__global__ __launch_bounds__(256) void attn_fin_k(
    const float* __restrict__ part, const float* __restrict__ temp,
    float* __restrict__ attn_out)
{
    const int bh = blockIdx.x;
    __shared__ float sm[16][16];
    const int tid = threadIdx.x;
    const int i2 = tid >> 4, j2 = tid & 15;

    float a = 0.f;
    #pragma unroll
    for (int sl = 0; sl < SLICES; sl++)
        a += part[((size_t)(sl * (B_*HEADS_) + bh)) * 256 + tid];
    a *= temp[j2];
    sm[i2][j2] = a;
    __syncthreads();

    if (tid < 16) {
        int j = tid;
        float mx = -1e30f;
        #pragma unroll
        for (int ii = 0; ii < 16; ii++) mx = fmaxf(mx, sm[ii][j]);
        float e[16]; float ssum = 0.f;
        #pragma unroll
        for (int ii = 0; ii < 16; ii++) { e[ii] = expf(sm[ii][j] - mx); ssum += e[ii]; }
        float inv = 1.f / ssum;
        #pragma unroll
        for (int ii = 0; ii < 16; ii++)
            attn_out[((size_t)bh * 16 + ii) * 16 + j] = e[ii] * inv;
    }
}

// ---------------- WfT (fp16) ----------------
__global__ __launch_bounds__(256) void wfused_k(const float* __restrict__ attn,
                                                const float* __restrict__ w_out,
                                                __half* __restrict__ wfTh)
{
    const int bh = blockIdx.x;
    const int b = bh >> 4, h = bh & 15;
    const int e = threadIdx.x;
    __shared__ float a[16][16];
    a[threadIdx.x >> 4][threadIdx.x & 15] = attn[(size_t)bh * 256 + threadIdx.x];
    __syncthreads();

    float w[16];
    #pragma unroll
    for (int j = 0; j < 16; j++) w[j] = w_out[(size_t)(h*16 + j) * DIM_ + e];
    #pragma unroll
    for (int d = 0; d < 16; d++) {
        float s = 0.f;
        #pragma unroll
        for (int j = 0; j < 16; j++) s += a[d][j] * w[j];
        wfTh[((size_t)b * DIM_ + e) * DIM_ + (h*16 + d)] = __float2half_rn(s);
    }
}

// ---------------- launch ----------------
extern "C" void kernel_launch(void* const* d_in, const int* in_sizes, int n_in,
                              void* d_out, int out_size)
{
    const float* x      = (const float*)d_in[0];
    const float* w_qkv  = (const float*)d_in[1];
    const float* w_dw   = (const float*)d_in[2];
    const float* w_out  = (const float*)d_in[3];
    const float* temp   = (const float*)d_in[4];
    const float* mean_q = (const float*)d_in[5];
    const float* var_q  = (const float*)d_in[6];
    const float* mean_k = (const float*)d_in[7];
    const float* var_k  = (const float*)d_in[8];
    float* out = (float*)d_out;

    __half *xh, *qkvh, *qkh, *vh, *wfTh, *wqkvTh;
    float *part, *attn;
    float2 *statq, *statk;
    cudaGetSymbolAddress((void**)&xh,     g_xh);
    cudaGetSymbolAddress((void**)&qkvh,   g_qkvh);
    cudaGetSymbolAddress((void**)&qkh,    g_qkh);
    cudaGetSymbolAddress((void**)&vh,     g_vh);
    cudaGetSymbolAddress((void**)&part,   g_part);
    cudaGetSymbolAddress((void**)&attn,   g_attn);
    cudaGetSymbolAddress((void**)&wfTh,   g_wfTh);
    cudaGetSymbolAddress((void**)&wqkvTh, g_wqkvTh);
    cudaGetSymbolAddress((void**)&statq,  g_statq);
    cudaGetSymbolAddress((void**)&statk,  g_statk);

    cudaFuncSetAttribute(mgemm_k<true>,  cudaFuncAttributeMaxDynamicSharedMemorySize, TM_SMEM);
    cudaFuncSetAttribute(mgemm_k<false>, cudaFuncAttributeMaxDynamicSharedMemorySize, TM_SMEM);

    // 0) convert operands to fp16 + build stat tables
    cvt_x_k<<<(M_TOTAL * DIM_ / 4 + 255) / 256, 256>>>(x, xh);
    transp_k<<<(N_QKV * DIM_ + 255) / 256, 256>>>(w_qkv, wqkvTh);
    stats_k<<<(HW_ + 255) / 256, 256>>>(mean_q, var_q, mean_k, var_k, statq, statk);

    // 1) QKV projection: fp16 mma + ldmatrix, SW64 staging, fp16 output
    mgemm_k<true><<<dim3(N_QKV / TM_BN, M_TOTAL / TM_BM), 128, TM_SMEM>>>(
        xh, DIM_, wqkvTh, DIM_, 0, qkvh, N_QKV, M_TOTAL, DIM_);

    // 2) depthwise conv (fp16 in) + q,k normalize; fp16 outputs
    dwconv_k<<<dim3(W_ / 32, H_ / 8, B_ * 48), 256>>>(
        qkvh, w_dw, qkh, vh, statq, statk);

    // 3) channel attention partials + reduce/softmax (fp32 accumulation)
    attn_part_k<<<dim3(B_ * HEADS_, SLICES), 256>>>(qkh, part);
    attn_fin_k<<<B_ * HEADS_, 256>>>(part, temp, attn);

    // 4) fold attn into output projection (fp16)
    wfused_k<<<B_ * HEADS_, 256>>>(attn, w_out, wfTh);

    // 5) out = v @ WfT[b]^T : fp16 mma + ldmatrix, SW64 staging, fp32 output
    mgemm_k<false><<<dim3(DIM_ / TM_BN, M_TOTAL / TM_BM), 128, TM_SMEM>>>(
        vh, DIM_, wfTh, DIM_, (long long)DIM_ * DIM_, out, DIM_, HW_, DIM_);
}

// round 17
// speedup vs baseline: 1.0055x; 1.0055x over previous
#include <cuda_runtime.h>
#include <cuda_fp16.h>
#include <math.h>
#include <stdint.h>

// ---------------- problem constants ----------------
#define B_      8
#define H_      128
#define W_      128
#define DIM_    256
#define HEADS_  16
#define DH_     16
#define HW_     (H_*W_)            // 16384
#define M_TOTAL (B_*HW_)           // 131072
#define N_QKV   (3*DIM_)           // 768
#define SLICES  8

// ---------------- scratch (no allocs -> __device__ globals) ----------------
__device__ __half g_xh   [(size_t)M_TOTAL * DIM_];    // fp16 x
__device__ __half g_qkvh [(size_t)M_TOTAL * N_QKV];   // pre-conv qkv (fp16)
__device__ __half g_qkh  [(size_t)M_TOTAL * 2 * DIM_];// post-conv NORMALIZED q,k (fp16)
__device__ __half g_vh   [(size_t)M_TOTAL * DIM_];    // post-conv v (fp16)
__device__ float  g_part [SLICES * B_ * HEADS_ * DH_ * DH_];
__device__ float  g_attn [B_ * HEADS_ * DH_ * DH_];
__device__ __half g_wfTh [B_ * DIM_ * DIM_];          // fused W^T per batch (fp16)
__device__ __half g_wqkvTh[N_QKV * DIM_];             // w_qkv^T (fp16)
__device__ float2 g_statq[HW_];                        // {mean_q, rsqrt(var_q)}
__device__ float2 g_statk[HW_];                        // {mean_k, rsqrt(var_k)}

// ---------------- helpers ----------------
__device__ __forceinline__ uint32_t smem_u32(const void* p) {
    uint32_t a;
    asm("{ .reg .u64 t; cvta.to.shared.u64 t, %1; cvt.u32.u64 %0, t; }" : "=r"(a) : "l"(p));
    return a;
}
__device__ __forceinline__ void cp16(uint32_t daddr, const void* g) {
    asm volatile("cp.async.ca.shared.global [%0], [%1], 16;" :: "r"(daddr), "l"(g));
}
#define CP_COMMIT() asm volatile("cp.async.commit_group;" ::: "memory")
#define CP_WAIT(n)  asm volatile("cp.async.wait_group %0;" :: "n"(n) : "memory")

__device__ __forceinline__ void mma_f16(float* c, const uint32_t* a, const uint32_t* b) {
    asm volatile(
        "mma.sync.aligned.m16n8k16.row.col.f32.f16.f16.f32 "
        "{%0,%1,%2,%3}, {%4,%5,%6,%7}, {%8,%9}, {%0,%1,%2,%3};"
        : "+f"(c[0]), "+f"(c[1]), "+f"(c[2]), "+f"(c[3])
        : "r"(a[0]), "r"(a[1]), "r"(a[2]), "r"(a[3]), "r"(b[0]), "r"(b[1]));
}
__device__ __forceinline__ void ldsm_x4(uint32_t& r0, uint32_t& r1, uint32_t& r2, uint32_t& r3,
                                        uint32_t addr) {
    asm volatile("ldmatrix.sync.aligned.m8n8.x4.shared.b16 {%0,%1,%2,%3}, [%4];"
        : "=r"(r0), "=r"(r1), "=r"(r2), "=r"(r3) : "r"(addr));
}

// ---------------- fp16 mma.sync GEMM: 128 thr, CTA 128x128, warp 64x64, 3-stage ----
// (R15 config — frozen; three smem variants measured equal, this one has lowest regs)
#define TM_BM 128
#define TM_BN 128
#define TM_BK 32
#define TM_PADH 40                            // halves/row
#define TM_ATILEH (TM_BM * TM_PADH)           // 5120 halves
#define TM_BTILEH (TM_BN * TM_PADH)           // 5120 halves
#define TM_STAGEH (TM_ATILEH + TM_BTILEH)     // 10240 halves = 20480 B
#define TM_NSTAGE 3
#define TM_SMEM  (TM_NSTAGE * TM_STAGEH * 2)  // 61440 B (dynamic)

template <bool HALF_OUT>
__global__ __launch_bounds__(128, 2) void mgemm_k(
    const __half* __restrict__ A, int lda,
    const __half* __restrict__ Bt, int ldb, long long b_stride,
    void* __restrict__ Cv, int ldc,
    int rows_per_batch, int K)
{
    extern __shared__ __half smh[];

    const int tid  = threadIdx.x;
    const int lane = tid & 31;
    const int wid  = tid >> 5;
    const int wm   = wid & 1;
    const int wn   = wid >> 1;
    const int gid  = lane >> 2;
    const int tig  = lane & 3;

    const int m0 = blockIdx.y * TM_BM;
    const int n0 = blockIdx.x * TM_BN;
    const int batch = m0 / rows_per_batch;
    const __half* Ap = A  + (size_t)m0 * lda;
    const __half* Bp = Bt + (size_t)batch * b_stride + (size_t)n0 * ldb;

    const uint32_t sbase = smem_u32(smh);
    const int arow  = (lane & 7) + ((lane >> 3) & 1) * 8;
    const int akcol = ((lane >> 4) & 1) * 8;
    const uint32_t a_lane = (uint32_t)(((wm * 64 + arow) * TM_PADH + akcol) * 2);
    const int brow  = (lane & 7) + ((lane >> 4) & 1) * 8;
    const int bkcol = ((lane >> 3) & 1) * 8;
    const uint32_t b_lane = (uint32_t)(TM_ATILEH * 2 + ((wn * 64 + brow) * TM_PADH + bkcol) * 2);

    float acc[4][8][4];
    #pragma unroll
    for (int mt = 0; mt < 4; mt++)
        #pragma unroll
        for (int nt = 0; nt < 8; nt++)
            #pragma unroll
            for (int r = 0; r < 4; r++) acc[mt][nt][r] = 0.f;

    const int nk = K / TM_BK;

    #define STAGE_LOAD(S, BUF) do {                                               \
        const __half* gA = Ap + (S) * TM_BK;                                       \
        const __half* gB = Bp + (S) * TM_BK;                                       \
        __half* sa = smh + (BUF) * TM_STAGEH;                                      \
        __half* sb = sa + TM_ATILEH;                                               \
        _Pragma("unroll")                                                          \
        for (int i = 0; i < 4; i++) {                                              \
            int idx = i * 128 + tid;                                               \
            int r = idx >> 2, c8 = idx & 3;                                        \
            cp16(smem_u32(sa + r * TM_PADH + c8 * 8), gA + (size_t)r * lda + c8 * 8); \
        }                                                                          \
        _Pragma("unroll")                                                          \
        for (int i = 0; i < 4; i++) {                                              \
            int idx = i * 128 + tid;                                               \
            int r = idx >> 2, c8 = idx & 3;                                        \
            cp16(smem_u32(sb + r * TM_PADH + c8 * 8), gB + (size_t)r * ldb + c8 * 8); \
        }                                                                          \
        CP_COMMIT();                                                               \
    } while (0)

    STAGE_LOAD(0, 0);
    if (nk > 1) STAGE_LOAD(1, 1);

    for (int s = 0; s < nk; s++) {
        const int buf = s % TM_NSTAGE;
        if (s + 2 < nk) { STAGE_LOAD(s + 2, (s + 2) % TM_NSTAGE); CP_WAIT(2); }
        else            { CP_WAIT(0); }
        __syncthreads();

        const uint32_t stg = sbase + (uint32_t)(buf * TM_STAGEH * 2);

        #pragma unroll
        for (int ks = 0; ks < 2; ks++) {
            const uint32_t koff = (uint32_t)(ks * 16 * 2);
            uint32_t bf[8][2];
            #pragma unroll
            for (int nt2 = 0; nt2 < 4; nt2++)
                ldsm_x4(bf[nt2*2][0], bf[nt2*2][1], bf[nt2*2+1][0], bf[nt2*2+1][1],
                        stg + b_lane + (uint32_t)(nt2 * 16 * TM_PADH * 2) + koff);
            #pragma unroll
            for (int mt = 0; mt < 4; mt++) {
                uint32_t af[4];
                ldsm_x4(af[0], af[1], af[2], af[3],
                        stg + a_lane + (uint32_t)(mt * 16 * TM_PADH * 2) + koff);
                #pragma unroll
                for (int nt = 0; nt < 8; nt++)
                    mma_f16(acc[mt][nt], af, bf[nt]);
            }
        }
        __syncthreads();
    }

    #pragma unroll
    for (int mt = 0; mt < 4; mt++) {
        #pragma unroll
        for (int nt = 0; nt < 8; nt++) {
            int row = m0 + wm * 64 + mt * 16 + gid;
            int col = n0 + wn * 64 + nt * 8 + tig * 2;
            if (HALF_OUT) {
                __half* C = (__half*)Cv;
                *(__half2*)(C + (size_t)row * ldc + col) =
                    __floats2half2_rn(acc[mt][nt][0], acc[mt][nt][1]);
                *(__half2*)(C + (size_t)(row + 8) * ldc + col) =
                    __floats2half2_rn(acc[mt][nt][2], acc[mt][nt][3]);
            } else {
                float* C = (float*)Cv;
                *(float2*)(C + (size_t)row * ldc + col) =
                    make_float2(acc[mt][nt][0], acc[mt][nt][1]);
                *(float2*)(C + (size_t)(row + 8) * ldc + col) =
                    make_float2(acc[mt][nt][2], acc[mt][nt][3]);
            }
        }
    }
}

// ---------------- cvt x -> fp16 copy ----------------
__global__ void cvt_x_k(const float* __restrict__ x, __half* __restrict__ xh) {
    size_t idx = (size_t)blockIdx.x * blockDim.x + threadIdx.x;
    if (idx >= ((size_t)M_TOTAL * DIM_) / 4) return;
    float4 v = ((const float4*)x)[idx];
    __half2 h0 = __floats2half2_rn(v.x, v.y);
    __half2 h1 = __floats2half2_rn(v.z, v.w);
    ((uint2*)xh)[idx] = make_uint2(*(uint32_t*)&h0, *(uint32_t*)&h1);
}

// ---------------- transpose + cvt + stat tables ----------------
__global__ void transp_k(const float* __restrict__ w, __half* __restrict__ wT) {
    int idx = blockIdx.x * blockDim.x + threadIdx.x;
    if (idx >= N_QKV * DIM_) return;
    int n = idx / DIM_, k = idx % DIM_;
    wT[idx] = __float2half_rn(w[(size_t)k * N_QKV + n]);
}

__global__ void stats_k(const float* __restrict__ mq, const float* __restrict__ vq,
                        const float* __restrict__ mk, const float* __restrict__ vk,
                        float2* __restrict__ sq, float2* __restrict__ sk) {
    int s = blockIdx.x * blockDim.x + threadIdx.x;
    if (s >= HW_) return;
    sq[s] = make_float2(mq[s], rsqrtf(vq[s]));
    sk[s] = make_float2(mk[s], rsqrtf(vk[s]));
}

// ---------------- depthwise 3x3 conv: fp16 smem tile, fp32 math, fp16 outputs ------
__global__ __launch_bounds__(256) void dwconv_k(
    const __half* __restrict__ in, const float* __restrict__ w,
    __half* __restrict__ qkh, __half* __restrict__ vh,
    const float2* __restrict__ statq, const float2* __restrict__ statk)
{
    __shared__ __half sm[10][34][16];   // 10880 B

    const int bx = blockIdx.x;
    const int by = blockIdx.y;
    const int bz = blockIdx.z;
    const int b  = bz / 48, g48 = bz % 48;
    const int cbase = g48 * 16;
    const bool is_v = (cbase >= 2 * DIM_);
    const float2* stats = (cbase >= DIM_) ? statk : statq;

    const int tid = threadIdx.x;

    // halo load: raw fp16, 2 uint4 (16 halves) per pixel
    for (int i = tid; i < 10 * 34 * 2; i += 256) {
        int c8 = i & 1;
        int x  = (i >> 1) % 34;
        int y  = (i >> 1) / 34;
        int gy = by * 8 - 1 + y, gx = bx * 32 - 1 + x;
        uint4 u = make_uint4(0u, 0u, 0u, 0u);
        if ((unsigned)gy < (unsigned)H_ && (unsigned)gx < (unsigned)W_)
            u = *(const uint4*)(in + ((size_t)(b * H_ + gy) * W_ + gx) * N_QKV + cbase + c8 * 8);
        *(uint4*)&sm[y][x][c8 * 8] = u;
    }

    const int c2s = tid & 7;
    const int xo  = tid >> 3;

    float2 wv[9];
    #pragma unroll
    for (int t = 0; t < 9; t++)
        wv[t] = *(const float2*)(w + (size_t)t * N_QKV + cbase + c2s * 2);
    __syncthreads();

    float2 rA[3], rB[3], rC[3];
    #pragma unroll
    for (int dx = 0; dx < 3; dx++) {
        rA[dx] = __half22float2(*(const __half2*)&sm[0][xo + dx][c2s * 2]);
        rB[dx] = __half22float2(*(const __half2*)&sm[1][xo + dx][c2s * 2]);
    }

    #pragma unroll
    for (int yo = 0; yo < 8; yo++) {
        #pragma unroll
        for (int dx = 0; dx < 3; dx++)
            rC[dx] = __half22float2(*(const __half2*)&sm[yo + 2][xo + dx][c2s * 2]);

        float2 acc = make_float2(0.f, 0.f);
        #pragma unroll
        for (int dx = 0; dx < 3; dx++) {
            acc.x += rA[dx].x * wv[dx].x;     acc.y += rA[dx].y * wv[dx].y;
        }
        #pragma unroll
        for (int dx = 0; dx < 3; dx++) {
            acc.x += rB[dx].x * wv[3 + dx].x; acc.y += rB[dx].y * wv[3 + dx].y;
        }
        #pragma unroll
        for (int dx = 0; dx < 3; dx++) {
            acc.x += rC[dx].x * wv[6 + dx].x; acc.y += rC[dx].y * wv[6 + dx].y;
        }

        int gy = by * 8 + yo, gx = bx * 32 + xo;
        size_t pix = (size_t)(b * H_ + gy) * W_ + gx;

        if (is_v) {
            *(__half2*)(vh + pix * DIM_ + (cbase - 2 * DIM_) + c2s * 2) =
                __floats2half2_rn(acc.x, acc.y);
        } else {
            float2 mv = stats[gy * W_ + gx];
            acc.x = (acc.x - mv.x) * mv.y;
            acc.y = (acc.y - mv.x) * mv.y;
            *(__half2*)(qkh + pix * (2 * DIM_) + cbase + c2s * 2) =
                __floats2half2_rn(acc.x, acc.y);
        }

        #pragma unroll
        for (int dx = 0; dx < 3; dx++) { rA[dx] = rB[dx]; rB[dx] = rC[dx]; }
    }
}

// ---------------- attention partials from fp16 normalized q,k ----------------
__global__ __launch_bounds__(256) void attn_part_k(
    const __half* __restrict__ qkh, float* __restrict__ part)
{
    const int bh = blockIdx.x;
    const int sl = blockIdx.y;
    const int b = bh >> 4, h = bh & 15;
    __shared__ float qs[64][16];
    __shared__ float ks[64][16];
    __shared__ float red[16][16][16];

    const int tid  = threadIdx.x;
    const int tile = tid & 15;
    const int g    = tid >> 4;
    const int it   = tile >> 2, jt = tile & 3;
    const int lrow = tid >> 2;
    const int lseg = tid & 3;
    const __half* base = qkh + (size_t)b * HW_ * (2 * DIM_) + h * DH_;

    float acc[4][4];
    #pragma unroll
    for (int a = 0; a < 4; a++)
        #pragma unroll
        for (int c = 0; c < 4; c++) acc[a][c] = 0.f;

    const int s_beg = sl * (HW_ / SLICES), s_end = s_beg + HW_ / SLICES;

    for (int s0 = s_beg; s0 < s_end; s0 += 64) {
        int s = s0 + lrow;
        const __half* pr = base + (size_t)s * (2 * DIM_);
        uint4 u;
        if (lseg < 2) u = *(const uint4*)(pr + lseg * 8);
        else          u = *(const uint4*)(pr + DIM_ + (lseg - 2) * 8);
        float* dst = (lseg < 2) ? &qs[lrow][(lseg & 1) * 8] : &ks[lrow][(lseg & 1) * 8];
        float2 f0 = __half22float2(*(__half2*)&u.x);
        float2 f1 = __half22float2(*(__half2*)&u.y);
        float2 f2 = __half22float2(*(__half2*)&u.z);
        float2 f3 = __half22float2(*(__half2*)&u.w);
        dst[0] = f0.x; dst[1] = f0.y; dst[2] = f1.x; dst[3] = f1.y;
        dst[4] = f2.x; dst[5] = f2.y; dst[6] = f3.x; dst[7] = f3.y;
        __syncthreads();

        #pragma unroll
        for (int t = 0; t < 4; t++) {
            int ss = g + t * 16;
            float4 kf = *(const float4*)&ks[ss][it * 4];
            float4 qf = *(const float4*)&qs[ss][jt * 4];
            acc[0][0] += kf.x * qf.x; acc[0][1] += kf.x * qf.y;
            acc[0][2] += kf.x * qf.z; acc[0][3] += kf.x * qf.w;
            acc[1][0] += kf.y * qf.x; acc[1][1] += kf.y * qf.y;
            acc[1][2] += kf.y * qf.z; acc[1][3] += kf.y * qf.w;
            acc[2][0] += kf.z * qf.x; acc[2][1] += kf.z * qf.y;
            acc[2][2] += kf.z * qf.z; acc[2][3] += kf.z * qf.w;
            acc[3][0] += kf.w * qf.x; acc[3][1] += kf.w * qf.y;
            acc[3][2] += kf.w * qf.z; acc[3][3] += kf.w * qf.w;
        }
        __syncthreads();
    }

    #pragma unroll
    for (int a = 0; a < 4; a++)
        #pragma unroll
        for (int c = 0; c < 4; c++)
            red[g][it * 4 + a][jt * 4 + c] = acc[a][c];
    __syncthreads();

    const int i2 = tid >> 4, j2 = tid & 15;
    float r = 0.f;
    #pragma unroll
    for (int gg = 0; gg < 16; gg++) r += red[gg][i2][j2];
    part[((size_t)(sl * (B_*HEADS_) + bh)) * 256 + i2 * 16 + j2] = r;
}

// ---------------- reduce slices + temperature + softmax(axis=-2) ----------------
__global__ __launch_bounds__(256) void attn_fin_k(
    const float* __restrict__ part, const float* __restrict__ temp,
    float* __restrict__ attn_out)
{
    const int bh = blockIdx.x;
    __shared__ float sm[16][16];
    const int tid = threadIdx.x;
    const int i2 = tid >> 4, j2 = tid & 15;

    float a = 0.f;
    #pragma unroll
    for (int sl = 0; sl < SLICES; sl++)
        a += part[((size_t)(sl * (B_*HEADS_) + bh)) * 256 + tid];
    a *= temp[j2];
    sm[i2][j2] = a;
    __syncthreads();

    if (tid < 16) {
        int j = tid;
        float mx = -1e30f;
        #pragma unroll
        for (int ii = 0; ii < 16; ii++) mx = fmaxf(mx, sm[ii][j]);
        float e[16]; float ssum = 0.f;
        #pragma unroll
        for (int ii = 0; ii < 16; ii++) { e[ii] = expf(sm[ii][j] - mx); ssum += e[ii]; }
        float inv = 1.f / ssum;
        #pragma unroll
        for (int ii = 0; ii < 16; ii++)
            attn_out[((size_t)bh * 16 + ii) * 16 + j] = e[ii] * inv;
    }
}

// ---------------- WfT (fp16) ----------------
__global__ __launch_bounds__(256) void wfused_k(const float* __restrict__ attn,
                                                const float* __restrict__ w_out,
                                                __half* __restrict__ wfTh)
{
    const int bh = blockIdx.x;
    const int b = bh >> 4, h = bh & 15;
    const int e = threadIdx.x;
    __shared__ float a[16][16];
    a[threadIdx.x >> 4][threadIdx.x & 15] = attn[(size_t)bh * 256 + threadIdx.x];
    __syncthreads();

    float w[16];
    #pragma unroll
    for (int j = 0; j < 16; j++) w[j] = w_out[(size_t)(h*16 + j) * DIM_ + e];
    #pragma unroll
    for (int d = 0; d < 16; d++) {
        float s = 0.f;
        #pragma unroll
        for (int j = 0; j < 16; j++) s += a[d][j] * w[j];
        wfTh[((size_t)b * DIM_ + e) * DIM_ + (h*16 + d)] = __float2half_rn(s);
    }
}

// ---------------- launch ----------------
extern "C" void kernel_launch(void* const* d_in, const int* in_sizes, int n_in,
                              void* d_out, int out_size)
{
    const float* x      = (const float*)d_in[0];
    const float* w_qkv  = (const float*)d_in[1];
    const float* w_dw   = (const float*)d_in[2];
    const float* w_out  = (const float*)d_in[3];
    const float* temp   = (const float*)d_in[4];
    const float* mean_q = (const float*)d_in[5];
    const float* var_q  = (const float*)d_in[6];
    const float* mean_k = (const float*)d_in[7];
    const float* var_k  = (const float*)d_in[8];
    float* out = (float*)d_out;

    __half *xh, *qkvh, *qkh, *vh, *wfTh, *wqkvTh;
    float *part, *attn;
    float2 *statq, *statk;
    cudaGetSymbolAddress((void**)&xh,     g_xh);
    cudaGetSymbolAddress((void**)&qkvh,   g_qkvh);
    cudaGetSymbolAddress((void**)&qkh,    g_qkh);
    cudaGetSymbolAddress((void**)&vh,     g_vh);
    cudaGetSymbolAddress((void**)&part,   g_part);
    cudaGetSymbolAddress((void**)&attn,   g_attn);
    cudaGetSymbolAddress((void**)&wfTh,   g_wfTh);
    cudaGetSymbolAddress((void**)&wqkvTh, g_wqkvTh);
    cudaGetSymbolAddress((void**)&statq,  g_statq);
    cudaGetSymbolAddress((void**)&statk,  g_statk);

    cudaFuncSetAttribute(mgemm_k<true>,  cudaFuncAttributeMaxDynamicSharedMemorySize, TM_SMEM);
    cudaFuncSetAttribute(mgemm_k<false>, cudaFuncAttributeMaxDynamicSharedMemorySize, TM_SMEM);

    // 0) convert operands to fp16 + build stat tables
    cvt_x_k<<<(M_TOTAL * DIM_ / 4 + 255) / 256, 256>>>(x, xh);
    transp_k<<<(N_QKV * DIM_ + 255) / 256, 256>>>(w_qkv, wqkvTh);
    stats_k<<<(HW_ + 255) / 256, 256>>>(mean_q, var_q, mean_k, var_k, statq, statk);

    // 1) QKV projection: fp16 mma + ldmatrix, 3-stage cp.async, fp16 output
    mgemm_k<true><<<dim3(N_QKV / TM_BN, M_TOTAL / TM_BM), 128, TM_SMEM>>>(
        xh, DIM_, wqkvTh, DIM_, 0, qkvh, N_QKV, M_TOTAL, DIM_);

    // 2) depthwise conv (fp16 smem) + q,k normalize; fp16 outputs
    dwconv_k<<<dim3(W_ / 32, H_ / 8, B_ * 48), 256>>>(
        qkvh, w_dw, qkh, vh, statq, statk);

    // 3) channel attention partials + reduce/softmax (fp32 accumulation)
    attn_part_k<<<dim3(B_ * HEADS_, SLICES), 256>>>(qkh, part);
    attn_fin_k<<<B_ * HEADS_, 256>>>(part, temp, attn);

    // 4) fold attn into output projection (fp16)
    wfused_k<<<B_ * HEADS_, 256>>>(attn, w_out, wfTh);

    // 5) out = v @ WfT[b]^T : fp16 mma + ldmatrix, 3-stage cp.async, fp32 output
    mgemm_k<false><<<dim3(DIM_ / TM_BN, M_TOTAL / TM_BM), 128, TM_SMEM>>>(
        vh, DIM_, wfTh, DIM_, (long long)DIM_ * DIM_, out, DIM_, HW_, DIM_);
}